// round 14
// baseline (speedup 1.0000x reference)
#include <cuda_runtime.h>
#include <cuda_bf16.h>
#include <cstdint>

#define BATCH 8192
#define DIM 10
#define ROWP 12            // padded pooled row: 48B, 16B-aligned
#define LOG2E 1.4426950408889634f

__device__ float g_pooled[BATCH * ROWP];

typedef unsigned long long u64;
typedef unsigned int u32;

__device__ __forceinline__ u64 pack2(float lo, float hi) {
    u64 r; asm("mov.b64 %0, {%1, %2};" : "=l"(r) : "f"(lo), "f"(hi)); return r;
}
__device__ __forceinline__ float2 unpack2(u64 v) {
    float2 f; asm("mov.b64 {%0, %1}, %2;" : "=f"(f.x), "=f"(f.y) : "l"(v)); return f;
}
__device__ __forceinline__ u64 fma2(u64 a, u64 b, u64 c) {
    u64 d; asm("fma.rn.f32x2 %0, %1, %2, %3;" : "=l"(d) : "l"(a), "l"(b), "l"(c)); return d;
}
__device__ __forceinline__ u64 mul2(u64 a, u64 b) {
    u64 d; asm("mul.rn.f32x2 %0, %1, %2;" : "=l"(d) : "l"(a), "l"(b)); return d;
}
__device__ __forceinline__ u64 add2(u64 a, u64 b) {
    u64 d; asm("add.rn.f32x2 %0, %1, %2;" : "=l"(d) : "l"(a), "l"(b)); return d;
}
__device__ __forceinline__ float ex2f(float x) {
    float y; asm("ex2.approx.f32 %0, %1;" : "=f"(y) : "f"(x)); return y;
}
__device__ __forceinline__ u32 smem_u32(const void* p) {
    u32 a;
    asm("{ .reg .u64 t; cvta.to.shared.u64 t, %1; cvt.u32.u64 %0, t; }"
        : "=r"(a) : "l"(p));
    return a;
}
__device__ __forceinline__ void lds128_2x64(u64& a, u64& b, u32 addr) {
    asm volatile("ld.shared.v2.b64 {%0, %1}, [%2];"
                 : "=l"(a), "=l"(b) : "r"(addr));
}
__device__ __forceinline__ u64 lds64(u32 addr) {
    u64 v; asm volatile("ld.shared.b64 %0, [%1];" : "=l"(v) : "r"(addr)); return v;
}
__device__ __forceinline__ void mbar_init(u32 mbar, u32 count) {
    asm volatile("mbarrier.init.shared.b64 [%0], %1;" :: "r"(mbar), "r"(count) : "memory");
}
__device__ __forceinline__ void mbar_expect_tx(u32 mbar, u32 bytes) {
    asm volatile("mbarrier.arrive.expect_tx.shared.b64 _, [%0], %1;"
                 :: "r"(mbar), "r"(bytes) : "memory");
}
__device__ __forceinline__ void bulk_g2s(u32 dst, const void* src, u32 bytes, u32 mbar) {
    asm volatile("cp.async.bulk.shared::cta.global.mbarrier::complete_tx::bytes "
                 "[%0], [%1], %2, [%3];"
                 :: "r"(dst), "l"(src), "r"(bytes), "r"(mbar) : "memory");
}
__device__ __forceinline__ void mbar_wait(u32 mbar, u32 parity) {
    asm volatile(
        "{\n\t"
        ".reg .pred P;\n\t"
        "WAIT_%=:\n\t"
        "mbarrier.try_wait.parity.acquire.cta.shared::cta.b64 P, [%0], %1, 0x989680;\n\t"
        "@P bra.uni DONE_%=;\n\t"
        "bra.uni WAIT_%=;\n\t"
        "DONE_%=:\n\t"
        "}"
        :: "r"(mbar), "r"(parity) : "memory");
}

// ---------------------------------------------------------------------------
// Kernel 1: pooled[b,:] = (sum_n w_n * x[b,n,:]) @ W   (stride-12 padded rows)
// ---------------------------------------------------------------------------
#define PK_NT 128
__global__ __launch_bounds__(PK_NT)
void pooled_kernel(const float* __restrict__ x,
                   const float* __restrict__ A,
                   const float* __restrict__ W) {
    __shared__ float sx[PK_NT * 3 * DIM];
    __shared__ float sW[DIM * DIM];
    __shared__ float sw[3];
    int tid = threadIdx.x;
    if (tid < DIM * DIM) sW[tid] = W[tid];
    if (tid < 3) {
        const float offsum[3] = {1.f, 1.f, 2.f};
        sw[tid] = 0.125f * (offsum[tid] + A[tid] + A[3 + tid]);
    }
    const float4* xs = (const float4*)(x + blockIdx.x * PK_NT * 3 * DIM);
    float4* sd = (float4*)sx;
    #pragma unroll
    for (int i = tid; i < PK_NT * 3 * DIM / 4; i += PK_NT)
        sd[i] = xs[i];
    __syncthreads();

    const float* xb = &sx[tid * 3 * DIM];
    float w0 = sw[0], w1 = sw[1], w2 = sw[2];
    float y[DIM];
    #pragma unroll
    for (int f = 0; f < DIM; f++)
        y[f] = fmaf(w2, xb[2 * DIM + f], fmaf(w1, xb[DIM + f], w0 * xb[f]));
    int b = blockIdx.x * PK_NT + tid;
    #pragma unroll
    for (int o = 0; o < DIM; o++) {
        float acc = 0.f;
        #pragma unroll
        for (int f = 0; f < DIM; f++)
            acc = fmaf(y[f], sW[f * DIM + o], acc);
        g_pooled[b * ROWP + o] = acc;
    }
    g_pooled[b * ROWP + 10] = 0.f;
    g_pooled[b * ROWP + 11] = 0.f;
}

// ---------------------------------------------------------------------------
// Kernel 2: out = softmax(P P^T) P, flash-style.
// NT=128, BQ=8, grid=1024, QPT=4, PARTS=64, KPT=2 (8 independent exp chains
// per iteration -> fma pipe stays fed with only 4 warps/SMSP).
// cp.async.bulk tile fills + mbarriers.
// ---------------------------------------------------------------------------
#define TILE 512
#define NTILES (BATCH / TILE)
#define NT 128
#define PARTS 64
#define QPT 4
#define KPT 2
#define BQ 8     // (NT/PARTS)*QPT
#define JITER (TILE / (PARTS * KPT))   // 4

#define TILE_BYTES (TILE * ROWP * 4)   // 24576

__global__ __launch_bounds__(NT, 4)
void attn_kernel(float* __restrict__ out) {
    __shared__ __align__(16) float sk[2][TILE * ROWP];   // 48 KB
    __shared__ __align__(8) u64 mbar_store[2];

    int tid  = threadIdx.x;
    int grp  = tid >> 6;        // 0..1 : query-quad group (2 warps)
    int p    = tid & 63;        // key-part within group
    int wid  = tid >> 5;        // warp 0..3
    int lane = tid & 31;
    int myq  = blockIdx.x * BQ + grp * QPT;

    u32 sbase = smem_u32(&sk[0][0]);
    u32 mbar0 = smem_u32(&mbar_store[0]);
    u32 mbar1 = mbar0 + 8;

    if (tid == 0) {
        mbar_init(mbar0, 1);
        mbar_init(mbar1, 1);
    }
    __syncthreads();

    // queries (pre-scaled by log2e)
    u64 q[QPT][5];
    #pragma unroll
    for (int u = 0; u < QPT; u++)
        #pragma unroll
        for (int h = 0; h < 5; h++) {
            float2 v = *(const float2*)&g_pooled[(myq + u) * ROWP + 2 * h];
            q[u][h] = pack2(v.x * LOG2E, v.y * LOG2E);
        }

    u64 acc[QPT][5];
    u64 esum01 = pack2(0.f, 0.f);
    u64 esum23 = pack2(0.f, 0.f);
    #pragma unroll
    for (int u = 0; u < QPT; u++)
        #pragma unroll
        for (int h = 0; h < 5; h++) acc[u][h] = pack2(0.f, 0.f);

    // kick tile 0 into buffer 0
    if (tid == 0) {
        mbar_expect_tx(mbar0, TILE_BYTES);
        bulk_g2s(sbase, g_pooled, TILE_BYTES, mbar0);
    }

    for (int t = 0; t < NTILES; t++) {
        int b = t & 1;
        if (t + 1 < NTILES && tid == 0) {
            u32 mb = (b ? mbar0 : mbar1);
            mbar_expect_tx(mb, TILE_BYTES);
            bulk_g2s(sbase + (1 - b) * TILE_BYTES,
                     g_pooled + (t + 1) * TILE * ROWP, TILE_BYTES, mb);
        }
        mbar_wait(b ? mbar1 : mbar0, (t >> 1) & 1);

        u32 addr = sbase + b * TILE_BYTES + p * 48u;

        #pragma unroll
        for (int it = 0; it < JITER; it++) {
            u32 oa = addr + (u32)(it * (PARTS * KPT * 48));
            u32 ob = oa + (u32)(PARTS * 48);
            u64 kA[5], kB[5];
            lds128_2x64(kA[0], kA[1], oa);
            lds128_2x64(kA[2], kA[3], oa + 16u);
            kA[4] = lds64(oa + 32u);
            lds128_2x64(kB[0], kB[1], ob);
            lds128_2x64(kB[2], kB[3], ob + 16u);
            kB[4] = lds64(ob + 32u);

            // 8 independent dot chains (4 queries x 2 keys)
            u64 sA0 = mul2(q[0][0], kA[0]);
            u64 sA1 = mul2(q[1][0], kA[0]);
            u64 sA2 = mul2(q[2][0], kA[0]);
            u64 sA3 = mul2(q[3][0], kA[0]);
            u64 sB0 = mul2(q[0][0], kB[0]);
            u64 sB1 = mul2(q[1][0], kB[0]);
            u64 sB2 = mul2(q[2][0], kB[0]);
            u64 sB3 = mul2(q[3][0], kB[0]);
            #pragma unroll
            for (int h = 1; h < 5; h++) {
                sA0 = fma2(q[0][h], kA[h], sA0);
                sA1 = fma2(q[1][h], kA[h], sA1);
                sA2 = fma2(q[2][h], kA[h], sA2);
                sA3 = fma2(q[3][h], kA[h], sA3);
                sB0 = fma2(q[0][h], kB[h], sB0);
                sB1 = fma2(q[1][h], kB[h], sB1);
                sB2 = fma2(q[2][h], kB[h], sB2);
                sB3 = fma2(q[3][h], kB[h], sB3);
            }
            float2 fA0 = unpack2(sA0);
            float2 fA1 = unpack2(sA1);
            float2 fA2 = unpack2(sA2);
            float2 fA3 = unpack2(sA3);
            float2 fB0 = unpack2(sB0);
            float2 fB1 = unpack2(sB1);
            float2 fB2 = unpack2(sB2);
            float2 fB3 = unpack2(sB3);
            float eA0 = ex2f(fA0.x + fA0.y);
            float eA1 = ex2f(fA1.x + fA1.y);
            float eA2 = ex2f(fA2.x + fA2.y);
            float eA3 = ex2f(fA3.x + fA3.y);
            float eB0 = ex2f(fB0.x + fB0.y);
            float eB1 = ex2f(fB1.x + fB1.y);
            float eB2 = ex2f(fB2.x + fB2.y);
            float eB3 = ex2f(fB3.x + fB3.y);
            esum01 = add2(esum01, pack2(eA0, eA1));
            esum23 = add2(esum23, pack2(eA2, eA3));
            esum01 = add2(esum01, pack2(eB0, eB1));
            esum23 = add2(esum23, pack2(eB2, eB3));
            u64 a0 = pack2(eA0, eA0);
            u64 a1 = pack2(eA1, eA1);
            u64 a2 = pack2(eA2, eA2);
            u64 a3 = pack2(eA3, eA3);
            u64 b0 = pack2(eB0, eB0);
            u64 b1 = pack2(eB1, eB1);
            u64 b2 = pack2(eB2, eB2);
            u64 b3 = pack2(eB3, eB3);
            #pragma unroll
            for (int h = 0; h < 5; h++) {
                acc[0][h] = fma2(a0, kA[h], acc[0][h]);
                acc[1][h] = fma2(a1, kA[h], acc[1][h]);
                acc[2][h] = fma2(a2, kA[h], acc[2][h]);
                acc[3][h] = fma2(a3, kA[h], acc[3][h]);
                acc[0][h] = fma2(b0, kB[h], acc[0][h]);
                acc[1][h] = fma2(b1, kB[h], acc[1][h]);
                acc[2][h] = fma2(b2, kB[h], acc[2][h]);
                acc[3][h] = fma2(b3, kB[h], acc[3][h]);
            }
        }
        __syncthreads();   // all threads done with buffer b before refill
    }

    // intra-warp reduction over 32 key-part lanes
    #pragma unroll
    for (int off = 16; off >= 1; off >>= 1) {
        {
            u64 o01 = __shfl_down_sync(0xffffffffu, esum01, off);
            u64 o23 = __shfl_down_sync(0xffffffffu, esum23, off);
            esum01 = add2(esum01, o01);
            esum23 = add2(esum23, o23);
        }
        #pragma unroll
        for (int u = 0; u < QPT; u++)
            #pragma unroll
            for (int h = 0; h < 5; h++) {
                u64 other = __shfl_down_sync(0xffffffffu, acc[u][h], off);
                acc[u][h] = add2(acc[u][h], other);
            }
    }

    // cross-warp combine via SMEM overlay (all tile reads done)
    float* sred = &sk[0][0];    // [warp][u][12]: 10 acc + esum
    if (lane == 0) {
        float2 es01 = unpack2(esum01);
        float2 es23 = unpack2(esum23);
        float est[QPT] = {es01.x, es01.y, es23.x, es23.y};
        #pragma unroll
        for (int u = 0; u < QPT; u++) {
            float* dst = sred + (wid * QPT + u) * 12;
            #pragma unroll
            for (int h = 0; h < 5; h++) {
                float2 v = unpack2(acc[u][h]);
                dst[2 * h] = v.x; dst[2 * h + 1] = v.y;
            }
            dst[10] = est[u];
        }
    }
    __syncthreads();

    // 2 groups x 4 queries x 10 feats = 80 output elements
    if (tid < BQ * DIM) {
        int g = tid / (QPT * DIM);
        int u = (tid / DIM) % QPT;
        int f = tid % DIM;
        const float* w0p = sred + ((2 * g) * QPT + u) * 12;
        const float* w1p = sred + ((2 * g + 1) * QPT + u) * 12;
        float v  = w0p[f] + w1p[f];
        float es = w0p[10] + w1p[10];
        out[(blockIdx.x * BQ + g * QPT + u) * DIM + f] = v / es;
    }
}

// ---------------------------------------------------------------------------
extern "C" void kernel_launch(void* const* d_in, const int* in_sizes, int n_in,
                              void* d_out, int out_size) {
    const float* x = (const float*)d_in[0];   // [8192, 3, 10]
    const float* A = (const float*)d_in[1];   // [3, 3]
    const float* W = (const float*)d_in[2];   // [10, 10]
    float* out = (float*)d_out;               // [8192, 10]

    pooled_kernel<<<BATCH / PK_NT, PK_NT>>>(x, A, W);
    attn_kernel<<<BATCH / BQ, NT>>>(out);
}

// round 16
// speedup vs baseline: 1.0850x; 1.0850x over previous
#include <cuda_runtime.h>
#include <cuda_bf16.h>
#include <cstdint>

#define BATCH 8192
#define DIM 10
#define ROWP 12            // padded pooled row: 48B; pads are ZERO (load-safe)
#define LOG2E 1.4426950408889634f

__device__ float g_pooled[BATCH * ROWP];

typedef unsigned long long u64;
typedef unsigned int u32;

__device__ __forceinline__ u64 pack2(float lo, float hi) {
    u64 r; asm("mov.b64 %0, {%1, %2};" : "=l"(r) : "f"(lo), "f"(hi)); return r;
}
__device__ __forceinline__ float2 unpack2(u64 v) {
    float2 f; asm("mov.b64 {%0, %1}, %2;" : "=f"(f.x), "=f"(f.y) : "l"(v)); return f;
}
__device__ __forceinline__ u64 fma2(u64 a, u64 b, u64 c) {
    u64 d; asm("fma.rn.f32x2 %0, %1, %2, %3;" : "=l"(d) : "l"(a), "l"(b), "l"(c)); return d;
}
__device__ __forceinline__ u64 add2(u64 a, u64 b) {
    u64 d; asm("add.rn.f32x2 %0, %1, %2;" : "=l"(d) : "l"(a), "l"(b)); return d;
}
__device__ __forceinline__ float ex2f(float x) {
    float y; asm("ex2.approx.f32 %0, %1;" : "=f"(y) : "f"(x)); return y;
}
__device__ __forceinline__ u32 f2tf32(float f) {
    u32 r; asm("cvt.rna.tf32.f32 %0, %1;" : "=r"(r) : "f"(f)); return r;
}
__device__ __forceinline__ u32 smem_u32(const void* p) {
    u32 a;
    asm("{ .reg .u64 t; cvta.to.shared.u64 t, %1; cvt.u32.u64 %0, t; }"
        : "=r"(a) : "l"(p));
    return a;
}
__device__ __forceinline__ void lds128_2x64(u64& a, u64& b, u32 addr) {
    asm volatile("ld.shared.v2.b64 {%0, %1}, [%2];"
                 : "=l"(a), "=l"(b) : "r"(addr));
}
__device__ __forceinline__ u64 lds64(u32 addr) {
    u64 v; asm volatile("ld.shared.b64 %0, [%1];" : "=l"(v) : "r"(addr)); return v;
}
__device__ __forceinline__ float ldsf32(u32 addr) {
    float v; asm volatile("ld.shared.f32 %0, [%1];" : "=f"(v) : "r"(addr)); return v;
}
__device__ __forceinline__ void mma_tf32(
    float& d0, float& d1, float& d2, float& d3,
    u32 a0, u32 a1, u32 a2, u32 a3, u32 b0, u32 b1,
    float c0, float c1, float c2, float c3) {
    asm volatile(
        "mma.sync.aligned.m16n8k8.row.col.f32.tf32.tf32.f32 "
        "{%0,%1,%2,%3}, {%4,%5,%6,%7}, {%8,%9}, {%10,%11,%12,%13};"
        : "=f"(d0), "=f"(d1), "=f"(d2), "=f"(d3)
        : "r"(a0), "r"(a1), "r"(a2), "r"(a3), "r"(b0), "r"(b1),
          "f"(c0), "f"(c1), "f"(c2), "f"(c3));
}
__device__ __forceinline__ void mbar_init(u32 mbar, u32 count) {
    asm volatile("mbarrier.init.shared.b64 [%0], %1;" :: "r"(mbar), "r"(count) : "memory");
}
__device__ __forceinline__ void mbar_expect_tx(u32 mbar, u32 bytes) {
    asm volatile("mbarrier.arrive.expect_tx.shared.b64 _, [%0], %1;"
                 :: "r"(mbar), "r"(bytes) : "memory");
}
__device__ __forceinline__ void bulk_g2s(u32 dst, const void* src, u32 bytes, u32 mbar) {
    asm volatile("cp.async.bulk.shared::cta.global.mbarrier::complete_tx::bytes "
                 "[%0], [%1], %2, [%3];"
                 :: "r"(dst), "l"(src), "r"(bytes), "r"(mbar) : "memory");
}
__device__ __forceinline__ void mbar_wait(u32 mbar, u32 parity) {
    asm volatile(
        "{\n\t"
        ".reg .pred P;\n\t"
        "WAIT_%=:\n\t"
        "mbarrier.try_wait.parity.acquire.cta.shared::cta.b64 P, [%0], %1, 0x989680;\n\t"
        "@P bra.uni DONE_%=;\n\t"
        "bra.uni WAIT_%=;\n\t"
        "DONE_%=:\n\t"
        "}"
        :: "r"(mbar), "r"(parity) : "memory");
}

// ---------------------------------------------------------------------------
// Kernel 1: pooled[b,:] = (sum_n w_n * x[b,n,:]) @ W   (stride-12, zero pads)
// ---------------------------------------------------------------------------
#define PK_NT 128
__global__ __launch_bounds__(PK_NT)
void pooled_kernel(const float* __restrict__ x,
                   const float* __restrict__ A,
                   const float* __restrict__ W) {
    __shared__ float sx[PK_NT * 3 * DIM];
    __shared__ float sW[DIM * DIM];
    __shared__ float sw[3];
    int tid = threadIdx.x;
    if (tid < DIM * DIM) sW[tid] = W[tid];
    if (tid < 3) {
        const float offsum[3] = {1.f, 1.f, 2.f};
        sw[tid] = 0.125f * (offsum[tid] + A[tid] + A[3 + tid]);
    }
    const float4* xs = (const float4*)(x + blockIdx.x * PK_NT * 3 * DIM);
    float4* sd = (float4*)sx;
    #pragma unroll
    for (int i = tid; i < PK_NT * 3 * DIM / 4; i += PK_NT)
        sd[i] = xs[i];
    __syncthreads();

    const float* xb = &sx[tid * 3 * DIM];
    float w0 = sw[0], w1 = sw[1], w2 = sw[2];
    float y[DIM];
    #pragma unroll
    for (int f = 0; f < DIM; f++)
        y[f] = fmaf(w2, xb[2 * DIM + f], fmaf(w1, xb[DIM + f], w0 * xb[f]));
    int b = blockIdx.x * PK_NT + tid;
    #pragma unroll
    for (int o = 0; o < DIM; o++) {
        float acc = 0.f;
        #pragma unroll
        for (int f = 0; f < DIM; f++)
            acc = fmaf(y[f], sW[f * DIM + o], acc);
        g_pooled[b * ROWP + o] = acc;
    }
    g_pooled[b * ROWP + 10] = 0.f;   // MUST be zero: read by mma k-step 2
    g_pooled[b * ROWP + 11] = 0.f;
}

// ---------------------------------------------------------------------------
// Kernel 2: out = softmax(P P^T) P — hybrid: S via tf32 mma.sync (tensor pipe),
// exp via MUFU, O-accumulate scalar fp32 from the C-fragment layout.
// CTA = 16 queries, 4 warps split keys; grid = 512. Bulk-copy tile fills.
// ---------------------------------------------------------------------------
#define TILE 512
#define NTILES (BATCH / TILE)
#define NT 128
#define BQ 16
#define NWARP 4
#define STEPS (TILE / (8 * NWARP))   // 16 eight-key steps per warp per tile

#define TILE_BYTES (TILE * ROWP * 4)   // 24576

__global__ __launch_bounds__(NT, 4)
void attn_kernel(float* __restrict__ out) {
    __shared__ __align__(16) float sk[2][TILE * ROWP];   // 48 KB
    __shared__ __align__(8) u64 mbar_store[2];

    int tid  = threadIdx.x;
    int wid  = tid >> 5;        // warp 0..3 = key partition
    int lane = tid & 31;
    int r    = lane >> 2;       // 0..7 : query row (also row+8)
    int c    = lane & 3;        // 0..3 : frag column
    int q0   = blockIdx.x * BQ;

    u32 sbase = smem_u32(&sk[0][0]);
    u32 mbar0 = smem_u32(&mbar_store[0]);
    u32 mbar1 = mbar0 + 8;

    if (tid == 0) {
        mbar_init(mbar0, 1);
        mbar_init(mbar1, 1);
    }
    __syncthreads();

    // --- Q fragments (A-layout, pre-scaled by log2e, tf32) ---
    // m16n8k8 tf32 A: a0=(g,ctg) a1=(g+8,ctg) a2=(g,ctg+4) a3=(g+8,ctg+4)
    const float* qr  = g_pooled + (q0 + r) * ROWP;
    const float* qr8 = g_pooled + (q0 + r + 8) * ROWP;
    u32 qa0 = f2tf32(LOG2E * qr[c]);
    u32 qa1 = f2tf32(LOG2E * qr8[c]);
    u32 qa2 = f2tf32(LOG2E * qr[c + 4]);
    u32 qa3 = f2tf32(LOG2E * qr8[c + 4]);
    u32 qp0 = f2tf32(LOG2E * qr[8 + c]);    // c>=2 reads zero pad -> 0
    u32 qp1 = f2tf32(LOG2E * qr8[8 + c]);

    // accumulators: O partials for rows r (oA) and r+8 (oB), this warp's keys
    u64 oA[5], oB[5];
    #pragma unroll
    for (int h = 0; h < 5; h++) { oA[h] = pack2(0.f, 0.f); oB[h] = pack2(0.f, 0.f); }
    float esumA = 0.f, esumB = 0.f;

    // kick tile 0 into buffer 0
    if (tid == 0) {
        mbar_expect_tx(mbar0, TILE_BYTES);
        bulk_g2s(sbase, g_pooled, TILE_BYTES, mbar0);
    }

    for (int t = 0; t < NTILES; t++) {
        int b = t & 1;
        if (t + 1 < NTILES && tid == 0) {
            u32 mb = (b ? mbar0 : mbar1);
            mbar_expect_tx(mb, TILE_BYTES);
            bulk_g2s(sbase + (1 - b) * TILE_BYTES,
                     g_pooled + (t + 1) * TILE * ROWP, TILE_BYTES, mb);
        }
        mbar_wait(b ? mbar1 : mbar0, (t >> 1) & 1);

        u32 kbase = sbase + b * TILE_BYTES;

        #pragma unroll 4
        for (int s = 0; s < STEPS; s++) {
            // this warp's 8-key chunk
            u32 base = kbase + (u32)((wid + NWARP * s) * 8 * 48);

            // B fragments: b0=(k=ctg, n=g)  b1=(k=ctg+4, n=g) -> K[key r][feat c / c+4]
            u32 brow = base + (u32)(r * 48 + c * 4);
            u32 b0 = f2tf32(ldsf32(brow));
            u32 b1 = f2tf32(ldsf32(brow + 16u));
            u32 bp = f2tf32(ldsf32(brow + 32u));   // feats 8+c (pads are 0)

            // acc keys (full fp32 rows): keys 2c and 2c+1 of this chunk
            u32 ka = base + (u32)(2 * c * 48);
            u64 kA0, kA1, kA2, kA3, kA4, kB0, kB1, kB2, kB3, kB4;
            lds128_2x64(kA0, kA1, ka);
            lds128_2x64(kA2, kA3, ka + 16u);
            kA4 = lds64(ka + 32u);
            lds128_2x64(kB0, kB1, ka + 48u);
            lds128_2x64(kB2, kB3, ka + 64u);
            kB4 = lds64(ka + 80u);

            // S = Q K^T via 2 tf32 mmas (k = feats 0-7, then 8-15 zero-padded)
            float s0, s1, s2, s3;
            mma_tf32(s0, s1, s2, s3, qa0, qa1, qa2, qa3, b0, b1,
                     0.f, 0.f, 0.f, 0.f);
            mma_tf32(s0, s1, s2, s3, qp0, qp1, 0u, 0u, bp, 0u,
                     s0, s1, s2, s3);

            // exp (already log2e-scaled)
            float e0 = ex2f(s0);   // (row r,   key 2c)
            float e1 = ex2f(s1);   // (row r,   key 2c+1)
            float e2 = ex2f(s2);   // (row r+8, key 2c)
            float e3 = ex2f(s3);   // (row r+8, key 2c+1)
            esumA += e0 + e1;
            esumB += e2 + e3;

            u64 ee0 = pack2(e0, e0);
            u64 ee1 = pack2(e1, e1);
            u64 ee2 = pack2(e2, e2);
            u64 ee3 = pack2(e3, e3);
            oA[0] = fma2(ee0, kA0, oA[0]);  oA[0] = fma2(ee1, kB0, oA[0]);
            oA[1] = fma2(ee0, kA1, oA[1]);  oA[1] = fma2(ee1, kB1, oA[1]);
            oA[2] = fma2(ee0, kA2, oA[2]);  oA[2] = fma2(ee1, kB2, oA[2]);
            oA[3] = fma2(ee0, kA3, oA[3]);  oA[3] = fma2(ee1, kB3, oA[3]);
            oA[4] = fma2(ee0, kA4, oA[4]);  oA[4] = fma2(ee1, kB4, oA[4]);
            oB[0] = fma2(ee2, kA0, oB[0]);  oB[0] = fma2(ee3, kB0, oB[0]);
            oB[1] = fma2(ee2, kA1, oB[1]);  oB[1] = fma2(ee3, kB1, oB[1]);
            oB[2] = fma2(ee2, kA2, oB[2]);  oB[2] = fma2(ee3, kB2, oB[2]);
            oB[3] = fma2(ee2, kA3, oB[3]);  oB[3] = fma2(ee3, kB3, oB[3]);
            oB[4] = fma2(ee2, kA4, oB[4]);  oB[4] = fma2(ee3, kB4, oB[4]);
        }
        __syncthreads();   // all threads done with buffer b before refill
    }

    // reduce across the 4 frag-columns (lanes within each quad)
    #pragma unroll
    for (int off = 1; off <= 2; off <<= 1) {
        esumA += __shfl_xor_sync(0xffffffffu, esumA, off);
        esumB += __shfl_xor_sync(0xffffffffu, esumB, off);
        #pragma unroll
        for (int h = 0; h < 5; h++) {
            oA[h] = add2(oA[h], __shfl_xor_sync(0xffffffffu, oA[h], off));
            oB[h] = add2(oB[h], __shfl_xor_sync(0xffffffffu, oB[h], off));
        }
    }

    // cross-warp combine via SMEM overlay: sred[warp][16 rows][12]
    float* sred = &sk[0][0];
    if (c == 0) {
        float* dA = sred + (wid * 16 + r) * 12;
        float* dB = sred + (wid * 16 + r + 8) * 12;
        #pragma unroll
        for (int h = 0; h < 5; h++) {
            float2 vA = unpack2(oA[h]);
            float2 vB = unpack2(oB[h]);
            dA[2 * h] = vA.x; dA[2 * h + 1] = vA.y;
            dB[2 * h] = vB.x; dB[2 * h + 1] = vB.y;
        }
        dA[10] = esumA;
        dB[10] = esumB;
    }
    __syncthreads();

    // 16 rows x 10 feats = 160 outputs  (FIX: strided loop, NT=128 < 160)
    for (int i = tid; i < BQ * DIM; i += NT) {
        int row = i / DIM;
        int f   = i % DIM;
        float v  = 0.f, es = 0.f;
        #pragma unroll
        for (int w = 0; w < NWARP; w++) {
            const float* src = sred + (w * 16 + row) * 12;
            v  += src[f];
            es += src[10];
        }
        out[(q0 + row) * DIM + f] = v / es;
    }
}

// ---------------------------------------------------------------------------
extern "C" void kernel_launch(void* const* d_in, const int* in_sizes, int n_in,
                              void* d_out, int out_size) {
    const float* x = (const float*)d_in[0];   // [8192, 3, 10]
    const float* A = (const float*)d_in[1];   // [3, 3]
    const float* W = (const float*)d_in[2];   // [10, 10]
    float* out = (float*)d_out;               // [8192, 10]

    pooled_kernel<<<BATCH / PK_NT, PK_NT>>>(x, A, W);
    attn_kernel<<<BATCH / BQ, NT>>>(out);
}

// round 17
// speedup vs baseline: 2.2223x; 2.0482x over previous
#include <cuda_runtime.h>
#include <cuda_bf16.h>
#include <cuda_fp16.h>
#include <cstdint>

#define BATCH 8192
#define DIM 10
#define ROWP 12            // fp32 pooled row stride (q loads); pads ZERO
#define LOG2E 1.4426950408889634f

#define TILE 512
#define NTILES (BATCH / TILE)
#define ROWH 520           // halves per KT row (512 keys + 8 pad -> 1040B)
#define ROWB (ROWH * 2)    // 1040
#define KT_TILE_BYTES (16 * ROWB)   // 16640

__device__ float g_pooled[BATCH * ROWP];
// KT, tiled: [tile][feat 0..15][key 0..519]; feat 10 = 1.0 (esum), 11-15 = 0
__device__ __align__(16) __half g_kt[NTILES * 16 * ROWH];

typedef unsigned long long u64;
typedef unsigned int u32;

__device__ __forceinline__ float ex2f(float x) {
    float y; asm("ex2.approx.f32 %0, %1;" : "=f"(y) : "f"(x)); return y;
}
__device__ __forceinline__ u32 f2tf32(float f) {
    u32 r; asm("cvt.rna.tf32.f32 %0, %1;" : "=r"(r) : "f"(f)); return r;
}
__device__ __forceinline__ u32 smem_u32(const void* p) {
    u32 a;
    asm("{ .reg .u64 t; cvta.to.shared.u64 t, %1; cvt.u32.u64 %0, t; }"
        : "=r"(a) : "l"(p));
    return a;
}
__device__ __forceinline__ u32 lds32(u32 addr) {
    u32 v; asm volatile("ld.shared.b32 %0, [%1];" : "=r"(v) : "r"(addr)); return v;
}
// load one fp16 from smem, widen to f32 (bits are exact tf32: 10-bit mantissa)
__device__ __forceinline__ float lds_h2f(u32 addr) {
    unsigned short h;
    asm volatile("ld.shared.u16 %0, [%1];" : "=h"(h) : "r"(addr));
    float f; asm("cvt.f32.f16 %0, %1;" : "=f"(f) : "h"(h));
    return f;
}
// pack two f32 -> f16x2 {lo, hi}  (PTX cvt d, hi, lo)
__device__ __forceinline__ u32 pack_f16x2(float lo, float hi) {
    u32 r; asm("cvt.rn.f16x2.f32 %0, %1, %2;" : "=r"(r) : "f"(hi), "f"(lo));
    return r;
}
__device__ __forceinline__ void mma_tf32(
    float& d0, float& d1, float& d2, float& d3,
    u32 a0, u32 a1, u32 a2, u32 a3, u32 b0, u32 b1,
    float c0, float c1, float c2, float c3) {
    asm volatile(
        "mma.sync.aligned.m16n8k8.row.col.f32.tf32.tf32.f32 "
        "{%0,%1,%2,%3}, {%4,%5,%6,%7}, {%8,%9}, {%10,%11,%12,%13};"
        : "=f"(d0), "=f"(d1), "=f"(d2), "=f"(d3)
        : "r"(a0), "r"(a1), "r"(a2), "r"(a3), "r"(b0), "r"(b1),
          "f"(c0), "f"(c1), "f"(c2), "f"(c3));
}
__device__ __forceinline__ void mma_f16(
    float& d0, float& d1, float& d2, float& d3,
    u32 a0, u32 a1, u32 a2, u32 a3, u32 b0, u32 b1,
    float c0, float c1, float c2, float c3) {
    asm volatile(
        "mma.sync.aligned.m16n8k16.row.col.f32.f16.f16.f32 "
        "{%0,%1,%2,%3}, {%4,%5,%6,%7}, {%8,%9}, {%10,%11,%12,%13};"
        : "=f"(d0), "=f"(d1), "=f"(d2), "=f"(d3)
        : "r"(a0), "r"(a1), "r"(a2), "r"(a3), "r"(b0), "r"(b1),
          "f"(c0), "f"(c1), "f"(c2), "f"(c3));
}
__device__ __forceinline__ void mbar_init(u32 mbar, u32 count) {
    asm volatile("mbarrier.init.shared.b64 [%0], %1;" :: "r"(mbar), "r"(count) : "memory");
}
__device__ __forceinline__ void mbar_expect_tx(u32 mbar, u32 bytes) {
    asm volatile("mbarrier.arrive.expect_tx.shared.b64 _, [%0], %1;"
                 :: "r"(mbar), "r"(bytes) : "memory");
}
__device__ __forceinline__ void bulk_g2s(u32 dst, const void* src, u32 bytes, u32 mbar) {
    asm volatile("cp.async.bulk.shared::cta.global.mbarrier::complete_tx::bytes "
                 "[%0], [%1], %2, [%3];"
                 :: "r"(dst), "l"(src), "r"(bytes), "r"(mbar) : "memory");
}
__device__ __forceinline__ void mbar_wait(u32 mbar, u32 parity) {
    asm volatile(
        "{\n\t"
        ".reg .pred P;\n\t"
        "WAIT_%=:\n\t"
        "mbarrier.try_wait.parity.acquire.cta.shared::cta.b64 P, [%0], %1, 0x989680;\n\t"
        "@P bra.uni DONE_%=;\n\t"
        "bra.uni WAIT_%=;\n\t"
        "DONE_%=:\n\t"
        "}"
        :: "r"(mbar), "r"(parity) : "memory");
}

// ---------------------------------------------------------------------------
// Kernel 1: pooled = (adj-weighted x) @ W -> g_pooled (fp32, q) + g_kt (fp16, KT)
// ---------------------------------------------------------------------------
#define PK_NT 128
__global__ __launch_bounds__(PK_NT)
void pooled_kernel(const float* __restrict__ x,
                   const float* __restrict__ A,
                   const float* __restrict__ W) {
    __shared__ float sx[PK_NT * 3 * DIM];
    __shared__ float sW[DIM * DIM];
    __shared__ float sw[3];
    int tid = threadIdx.x;
    if (tid < DIM * DIM) sW[tid] = W[tid];
    if (tid < 3) {
        const float offsum[3] = {1.f, 1.f, 2.f};
        sw[tid] = 0.125f * (offsum[tid] + A[tid] + A[3 + tid]);
    }
    const float4* xs = (const float4*)(x + blockIdx.x * PK_NT * 3 * DIM);
    float4* sd = (float4*)sx;
    #pragma unroll
    for (int i = tid; i < PK_NT * 3 * DIM / 4; i += PK_NT)
        sd[i] = xs[i];
    __syncthreads();

    const float* xb = &sx[tid * 3 * DIM];
    float w0 = sw[0], w1 = sw[1], w2 = sw[2];
    float y[DIM];
    #pragma unroll
    for (int f = 0; f < DIM; f++)
        y[f] = fmaf(w2, xb[2 * DIM + f], fmaf(w1, xb[DIM + f], w0 * xb[f]));
    int b = blockIdx.x * PK_NT + tid;
    int tile = b >> 9;
    int col  = b & 511;
    __half* kt = g_kt + tile * 16 * ROWH;
    #pragma unroll
    for (int o = 0; o < DIM; o++) {
        float acc = 0.f;
        #pragma unroll
        for (int f = 0; f < DIM; f++)
            acc = fmaf(y[f], sW[f * DIM + o], acc);
        g_pooled[b * ROWP + o] = acc;
        kt[o * ROWH + col] = __float2half(acc);
    }
    g_pooled[b * ROWP + 10] = 0.f;   // q pads MUST be zero (S mma k-step 2)
    g_pooled[b * ROWP + 11] = 0.f;
    kt[10 * ROWH + col] = __float2half(1.0f);   // esum ones-row
    #pragma unroll
    for (int f = 11; f < 16; f++)
        kt[f * ROWH + col] = __float2half(0.0f);
}

// ---------------------------------------------------------------------------
// Kernel 2: out = softmax(P P^T) P — full tensor-core:
//   S  = Q K^T  via tf32 m16n8k8 (verified R15 path; K from fp16 = exact tf32)
//   O^T = K^T E^T via fp16 m16n8k16 (C-frag of S == B-frag of O^T; no shuffles)
//   esum = O^T row 10 (ones-row in KT)
// CTA = 16 queries, 4 warps split keys; grid = 512; bulk-copy KT tile fills.
// ---------------------------------------------------------------------------
#define NT 128
#define BQ 16
#define NWARP 4
#define MACROS (TILE / (16 * NWARP))   // 8 sixteen-key macro steps per warp

__global__ __launch_bounds__(NT, 4)
void attn_kernel(float* __restrict__ out) {
    __shared__ __align__(16) char skt[2][KT_TILE_BYTES];   // 33280 B
    __shared__ float sred[NWARP][16][17];
    __shared__ __align__(8) u64 mbar_store[2];

    int tid  = threadIdx.x;
    int wid  = tid >> 5;        // warp 0..3 = key partition
    int lane = tid & 31;
    int r    = lane >> 2;       // g: query row / feat row (0..7)
    int c    = lane & 3;        // ctg
    int q0   = blockIdx.x * BQ;

    u32 sbase = smem_u32(&skt[0][0]);
    u32 mbar0 = smem_u32(&mbar_store[0]);
    u32 mbar1 = mbar0 + 8;

    if (tid == 0) {
        mbar_init(mbar0, 1);
        mbar_init(mbar1, 1);
    }
    __syncthreads();

    // --- Q fragments (tf32, pre-scaled by log2e) — identical to R15 ---
    const float* qr  = g_pooled + (q0 + r) * ROWP;
    const float* qr8 = g_pooled + (q0 + r + 8) * ROWP;
    u32 qa0 = f2tf32(LOG2E * qr[c]);
    u32 qa1 = f2tf32(LOG2E * qr8[c]);
    u32 qa2 = f2tf32(LOG2E * qr[c + 4]);
    u32 qa3 = f2tf32(LOG2E * qr8[c + 4]);
    u32 qp0 = f2tf32(LOG2E * qr[8 + c]);   // pads zero
    u32 qp1 = f2tf32(LOG2E * qr8[8 + c]);

    // O^T accumulators: oT1 = queries 0-7, oT2 = queries 8-15
    float o10 = 0.f, o11 = 0.f, o12 = 0.f, o13 = 0.f;
    float o20 = 0.f, o21 = 0.f, o22 = 0.f, o23 = 0.f;

    const char* gkt = (const char*)g_kt;
    if (tid == 0) {
        mbar_expect_tx(mbar0, KT_TILE_BYTES);
        bulk_g2s(sbase, gkt, KT_TILE_BYTES, mbar0);
    }

    for (int t = 0; t < NTILES; t++) {
        int b = t & 1;
        if (t + 1 < NTILES && tid == 0) {
            u32 mb = (b ? mbar0 : mbar1);
            mbar_expect_tx(mb, KT_TILE_BYTES);
            bulk_g2s(sbase + (1 - b) * KT_TILE_BYTES,
                     gkt + (t + 1) * KT_TILE_BYTES, KT_TILE_BYTES, mb);
        }
        mbar_wait(b ? mbar1 : mbar0, (t >> 1) & 1);

        u32 kb = sbase + b * KT_TILE_BYTES;

        #pragma unroll
        for (int m = 0; m < MACROS; m++) {
            int k0 = (m * NWARP + wid) * 16;   // this warp's 16-key chunk

            // O^T A-fragments: KT[feat][keys] fp16 pairs (conflict-free)
            u32 aoff = kb + (u32)(r * ROWB + (k0 + 2 * c) * 2);
            u32 a0 = lds32(aoff);
            u32 a1 = lds32(aoff + (u32)(8 * ROWB));
            u32 a2 = lds32(aoff + 16u);
            u32 a3 = lds32(aoff + (u32)(8 * ROWB) + 16u);

            // ---- S step A: keys k0 + r (lower 8 of chunk) ----
            u32 ba = kb + (u32)(c * ROWB + (k0 + r) * 2);
            float fb0 = lds_h2f(ba);
            float fb1 = lds_h2f(ba + (u32)(4 * ROWB));
            float fbp = lds_h2f(ba + (u32)(8 * ROWB));
            float s0, s1, s2, s3;
            mma_tf32(s0, s1, s2, s3, qa0, qa1, qa2, qa3,
                     __float_as_uint(fb0), __float_as_uint(fb1),
                     0.f, 0.f, 0.f, 0.f);
            mma_tf32(s0, s1, s2, s3, qp0, qp1, 0u, 0u,
                     __float_as_uint(fbp), 0u, s0, s1, s2, s3);
            float eA0 = ex2f(s0), eA1 = ex2f(s1), eA2 = ex2f(s2), eA3 = ex2f(s3);
            u32 pA_lo = pack_f16x2(eA0, eA1);   // queries 0-7 grp, keys 2c,2c+1
            u32 pA_hi = pack_f16x2(eA2, eA3);   // queries 8-15 grp

            // ---- S step B: keys k0 + 8 + r ----
            u32 bb = ba + 16u;
            float gb0 = lds_h2f(bb);
            float gb1 = lds_h2f(bb + (u32)(4 * ROWB));
            float gbp = lds_h2f(bb + (u32)(8 * ROWB));
            mma_tf32(s0, s1, s2, s3, qa0, qa1, qa2, qa3,
                     __float_as_uint(gb0), __float_as_uint(gb1),
                     0.f, 0.f, 0.f, 0.f);
            mma_tf32(s0, s1, s2, s3, qp0, qp1, 0u, 0u,
                     __float_as_uint(gbp), 0u, s0, s1, s2, s3);
            float eB0 = ex2f(s0), eB1 = ex2f(s1), eB2 = ex2f(s2), eB3 = ex2f(s3);
            u32 pB_lo = pack_f16x2(eB0, eB1);
            u32 pB_hi = pack_f16x2(eB2, eB3);

            // ---- O^T += KT(chunk) x E(chunk): 2 fp16 mmas ----
            mma_f16(o10, o11, o12, o13, a0, a1, a2, a3, pA_lo, pB_lo,
                    o10, o11, o12, o13);
            mma_f16(o20, o21, o22, o23, a0, a1, a2, a3, pA_hi, pB_hi,
                    o20, o21, o22, o23);
        }
        __syncthreads();   // buffer b fully consumed before refill
    }

    // ---- epilogue: O^T frags -> smem, combine 4 warps, divide by esum ----
    // d0=(feat r, q 2c) d1=(feat r, q 2c+1) d2=(feat r+8, q 2c) d3=(feat r+8, q 2c+1)
    sred[wid][r][2 * c]         = o10;
    sred[wid][r][2 * c + 1]     = o11;
    sred[wid][r + 8][2 * c]     = o12;
    sred[wid][r + 8][2 * c + 1] = o13;
    sred[wid][r][8 + 2 * c]         = o20;
    sred[wid][r][8 + 2 * c + 1]     = o21;
    sred[wid][r + 8][8 + 2 * c]     = o22;
    sred[wid][r + 8][8 + 2 * c + 1] = o23;
    __syncthreads();

    for (int i = tid; i < BQ * DIM; i += NT) {
        int qq = i / DIM;
        int f  = i % DIM;
        float v  = 0.f, es = 0.f;
        #pragma unroll
        for (int w = 0; w < NWARP; w++) {
            v  += sred[w][f][qq];
            es += sred[w][10][qq];
        }
        out[(q0 + qq) * DIM + f] = v / es;
    }
}

// ---------------------------------------------------------------------------
extern "C" void kernel_launch(void* const* d_in, const int* in_sizes, int n_in,
                              void* d_out, int out_size) {
    const float* x = (const float*)d_in[0];   // [8192, 3, 10]
    const float* A = (const float*)d_in[1];   // [3, 3]
    const float* W = (const float*)d_in[2];   // [10, 10]
    float* out = (float*)d_out;               // [8192, 10]

    pooled_kernel<<<BATCH / PK_NT, PK_NT>>>(x, A, W);
    attn_kernel<<<BATCH / BQ, NT>>>(out);
}